// round 13
// baseline (speedup 1.0000x reference)
#include <cuda_runtime.h>
#include <cstdint>

// ---------------------------------------------------------------------------
// ActivityDecaySNN: 3-layer LIF SNN forward. T=50, B=512, 784->800->800->10.
// BITWISE CONSTRAINT: currents must reproduce the reference's ascending-k fp32
// FMA chain per element. GEMM1: scalar SIMT SGEMM (FFMA issue roofline).
// GEMM2: sparse ascending gather of W2T rows driven by spike masks; R13:
// 64-bit mask runs + 2-deep software pipeline (fewer pipeline drains; adds
// still strictly ascending-k -> bitwise identical).
// d_out: out[512*10] | s1r[50*512*800] | s2r[50*512*800] | s3r[50*512*10]
// ---------------------------------------------------------------------------

#define T_STEPS 50
#define BATCH   512
#define DIN     784
#define HID     800
#define NOUT    10
#define M_ROWS  (T_STEPS * BATCH)   // 25600
#define SBK     128                 // GEMM2 k-rows per tile
#define NT2     7                   // 6 full tiles + 1 of 32 rows
#define BH4F    (BATCH * HID / 4)   // 102400

__device__ float    g_c1[(size_t)M_ROWS * HID];
__device__ float    g_c2[(size_t)M_ROWS * HID];
__device__ float    g_c3[(size_t)M_ROWS * NOUT];
__device__ float    g_w2t[(size_t)HID * HID];
__device__ uint32_t g_masks[(size_t)M_ROWS * NT2 * 4];   // 2.87 MB

// ===========================================================================
// W2 transpose: W2T[k][n] = W2[n][k]. 32x32 tiles.
// ===========================================================================
__global__ void transpose_w2(const float* __restrict__ W, float* __restrict__ WT)
{
    __shared__ float t[32][33];
    const int bx = blockIdx.x * 32, by = blockIdx.y * 32;
    #pragma unroll
    for (int r = 0; r < 4; ++r)
        t[threadIdx.y + r * 8][threadIdx.x] =
            W[(size_t)(by + threadIdx.y + r * 8) * HID + bx + threadIdx.x];
    __syncthreads();
    #pragma unroll
    for (int r = 0; r < 4; ++r)
        WT[(size_t)(bx + threadIdx.y + r * 8) * HID + by + threadIdx.x] =
            t[threadIdx.x][threadIdx.y + r * 8];
}

// ===========================================================================
// LIF layer 1 + spike-mask emission (unchanged from R11).
// ===========================================================================
__global__ void lif1_mask(const float4* __restrict__ cur,
                          float4* __restrict__ spk,
                          uint32_t* __restrict__ masks,
                          const float* __restrict__ beta_ptr)
{
    const int idx = blockIdx.x * blockDim.x + threadIdx.x;   // [0, 102400)
    const int lane = threadIdx.x & 31;
    const int b    = idx / 200;
    const int h4   = idx % 200;
    const int hb4  = h4 & ~7;
    const int tile = hb4 >> 5;
    const int word = (hb4 >> 3) & 3;
    const bool wr  = ((lane & 7) == 0);
    const int sh   = 4 * (lane & 7);

    const float beta = fminf(fmaxf(beta_ptr[0], 0.0f), 1.0f);
    float4 mem = make_float4(0.f, 0.f, 0.f, 0.f);
    float4 rst = make_float4(0.f, 0.f, 0.f, 0.f);
    #pragma unroll
    for (int t = 0; t < T_STEPS; ++t) {
        const float4 c = cur[(size_t)t * BH4F + idx];
        float4 s;
        mem.x = beta * mem.x + c.x - rst.x; s.x = (mem.x - 1.0f > 0.0f) ? 1.0f : 0.0f;
        mem.y = beta * mem.y + c.y - rst.y; s.y = (mem.y - 1.0f > 0.0f) ? 1.0f : 0.0f;
        mem.z = beta * mem.z + c.z - rst.z; s.z = (mem.z - 1.0f > 0.0f) ? 1.0f : 0.0f;
        mem.w = beta * mem.w + c.w - rst.w; s.w = (mem.w - 1.0f > 0.0f) ? 1.0f : 0.0f;
        spk[(size_t)t * BH4F + idx] = s;
        rst = s;

        uint32_t nib = (s.x != 0.0f ? 1u : 0u) | (s.y != 0.0f ? 2u : 0u)
                     | (s.z != 0.0f ? 4u : 0u) | (s.w != 0.0f ? 8u : 0u);
        uint32_t wv = nib << sh;
        wv |= __shfl_xor_sync(0xffffffffu, wv, 1);
        wv |= __shfl_xor_sync(0xffffffffu, wv, 2);
        wv |= __shfl_xor_sync(0xffffffffu, wv, 4);
        if (wr) {
            const int m = t * BATCH + b;
            masks[((size_t)m * NT2 + tile) * 4 + word] = wv;
        }
    }
}

// ===========================================================================
// Sparse GEMM2: C2[m,n] = b2[n] + sum_{k active(m), ascending} W2T[k][n]
// Block: 64 m x 128 n; 8 warps, warp owns 8 m-rows. 3 blocks/SM (24 warps).
// W2T staged in 128-row k-tiles (64 KB); block's 64 mask uint4s staged too.
// Inner loop: 64-bit mask runs, 2-deep pipelined ffs gather (two W-rows in
// flight). Adds execute in exactly ascending-k order -> bitwise identical.
// ===========================================================================
#define G2_MROWS 64

__global__ __launch_bounds__(256, 3)
void gemm2_sparse(const uint32_t* __restrict__ masks,
                  const float* __restrict__ WT,
                  const float* __restrict__ bias, float* __restrict__ C)
{
    extern __shared__ float wt[];            // SBK*128 floats + 64 uint4 masks
    uint4* wmask = reinterpret_cast<uint4*>(wt + SBK * 128);

    const int tid   = threadIdx.x;
    const int warp  = tid >> 5;
    const int lane  = tid & 31;
    const int n0    = blockIdx.x * 128;
    const int m0    = blockIdx.y * G2_MROWS;
    const int m0w   = m0 + warp * 8;
    const int lane4 = lane * 4;

    float acc[8][4];
    #pragma unroll
    for (int mi = 0; mi < 8; ++mi)
        #pragma unroll
        for (int j = 0; j < 4; ++j) acc[mi][j] = 0.0f;

#define ACCADD(V)                                                    \
    { acc[mi][0] += (V).x; acc[mi][1] += (V).y;                      \
      acc[mi][2] += (V).z; acc[mi][3] += (V).w; }

    #pragma unroll
    for (int t = 0; t < NT2; ++t) {
        const int rows   = (t < 6) ? SBK : 32;
        const int chunks = rows * 32;
        __syncthreads();   // protect previous tile before restage
        #pragma unroll
        for (int p = 0; p < 16; ++p) {
            const int i = tid + p * 256;
            if (i < chunks) {
                const int row = i >> 5, c4 = i & 31;
                const int gn  = n0 + c4 * 4;
                const float4 v = (gn < HID)
                    ? *reinterpret_cast<const float4*>(WT + (size_t)(t * SBK + row) * HID + gn)
                    : make_float4(0.f, 0.f, 0.f, 0.f);
                *reinterpret_cast<float4*>(&wt[row * 128 + c4 * 4]) = v;
            }
        }
        if (tid < G2_MROWS)
            wmask[tid] = __ldg(reinterpret_cast<const uint4*>(
                masks + ((size_t)(m0 + tid) * NT2 + t) * 4));
        __syncthreads();

        #pragma unroll
        for (int mi = 0; mi < 8; ++mi) {
            const uint4 mv = wmask[warp * 8 + mi];   // broadcast LDS
            unsigned long long bw[2];
            if (t < 6) {
                bw[0] = (unsigned long long)mv.x | ((unsigned long long)mv.y << 32);
                bw[1] = (unsigned long long)mv.z | ((unsigned long long)mv.w << 32);
            } else {
                bw[0] = (unsigned long long)mv.x;   // last tile: 32 valid bits
                bw[1] = 0ull;
            }
            #pragma unroll
            for (int h = 0; h < 2; ++h) {
                unsigned long long bits = bw[h];
                if (!bits) continue;
                const float* wb = wt + (size_t)h * 64 * 128 + lane4;
                int k0 = __ffsll(bits) - 1;
                bits &= bits - 1;
                float4 v0 = *reinterpret_cast<const float4*>(wb + k0 * 128);
                if (!bits) { ACCADD(v0); continue; }
                int k1 = __ffsll(bits) - 1;
                bits &= bits - 1;
                float4 v1 = *reinterpret_cast<const float4*>(wb + k1 * 128);
                while (bits) {
                    const int k2 = __ffsll(bits) - 1;
                    bits &= bits - 1;
                    const float4 v2 = *reinterpret_cast<const float4*>(wb + k2 * 128);
                    ACCADD(v0);
                    v0 = v1;
                    v1 = v2;
                }
                ACCADD(v0);
                ACCADD(v1);
            }
        }
    }
#undef ACCADD

    // ---- epilogue: bias + store ----
    const int gn = n0 + lane4;
    if (gn < HID) {
        const float4 b = *reinterpret_cast<const float4*>(bias + gn);
        #pragma unroll
        for (int mi = 0; mi < 8; ++mi) {
            float4 v;
            v.x = acc[mi][0] + b.x;
            v.y = acc[mi][1] + b.y;
            v.z = acc[mi][2] + b.z;
            v.w = acc[mi][3] + b.w;
            *reinterpret_cast<float4*>(C + (size_t)(m0w + mi) * HID + gn) = v;
        }
    }
}

// ===========================================================================
// Dense SIMT SGEMM (NT) for layer 1 — R4/R7 version (bitwise, at FFMA floor).
// ===========================================================================
template<int BK>
__global__ __launch_bounds__(256, 2)
void sgemm_nt(const float* __restrict__ A, const float* __restrict__ W,
              const float* __restrict__ bias, float* __restrict__ C,
              int M, int N, int K)
{
    constexpr int QPR    = BK / 4;
    constexpr int ROWSPP = 256 / QPR;
    constexpr int NQ     = BK / 8;
    constexpr int HQ     = NQ / 2;

    extern __shared__ float sm[];
    float* As = sm;
    float* Ws = sm + 2 * BK * 128;

    const int tid = threadIdx.x;
    const int tx  = tid & 15;
    const int ty  = tid >> 4;
    const int m0  = blockIdx.y * 128;
    const int n0  = blockIdx.x * 128;

    const int ldCol = (tid % QPR) * 4;
    const int ldRow = tid / QPR;

    float acc[8][8];
    #pragma unroll
    for (int i = 0; i < 8; ++i)
        #pragma unroll
        for (int j = 0; j < 8; ++j) acc[i][j] = 0.0f;

    const int numTiles = K / BK;
    const float4 z4 = make_float4(0.f, 0.f, 0.f, 0.f);

    #pragma unroll
    for (int p = 0; p < NQ; ++p) {
        const int r  = ldRow + p * ROWSPP;
        const float4 av = *reinterpret_cast<const float4*>(A + (size_t)(m0 + r) * K + ldCol);
        const int wn = n0 + r;
        const float4 wv = (wn < N)
            ? *reinterpret_cast<const float4*>(W + (size_t)wn * K + ldCol) : z4;
        #pragma unroll
        for (int q = 0; q < 4; ++q) {
            As[(ldCol + q) * 128 + r] = (&av.x)[q];
            Ws[(ldCol + q) * 128 + r] = (&wv.x)[q];
        }
    }
    __syncthreads();

    for (int t = 0; t < numTiles; ++t) {
        const int  buf     = t & 1;
        const int  nb      = buf ^ 1;
        const bool hasNext = (t + 1 < numTiles);
        const int  kn      = (t + 1) * BK;

        float* Ab = As + buf * BK * 128;
        float* Wb = Ws + buf * BK * 128;
        float* An = As + nb * BK * 128;
        float* Wn = Ws + nb * BK * 128;

        float4 pa[HQ], pw[HQ];

        if (hasNext) {
            #pragma unroll
            for (int p = 0; p < HQ; ++p) {
                const int r = ldRow + p * ROWSPP;
                pa[p] = *reinterpret_cast<const float4*>(A + (size_t)(m0 + r) * K + kn + ldCol);
                const int wn = n0 + r;
                pw[p] = (wn < N)
                    ? *reinterpret_cast<const float4*>(W + (size_t)wn * K + kn + ldCol) : z4;
            }
        }
        #pragma unroll
        for (int kk = 0; kk < BK / 2; ++kk) {
            float af[8], wf[8];
            *reinterpret_cast<float4*>(&af[0]) = *reinterpret_cast<const float4*>(Ab + kk * 128 + ty * 8);
            *reinterpret_cast<float4*>(&af[4]) = *reinterpret_cast<const float4*>(Ab + kk * 128 + ty * 8 + 4);
            *reinterpret_cast<float4*>(&wf[0]) = *reinterpret_cast<const float4*>(Wb + kk * 128 + tx * 4);
            *reinterpret_cast<float4*>(&wf[4]) = *reinterpret_cast<const float4*>(Wb + kk * 128 + 64 + tx * 4);
            #pragma unroll
            for (int i = 0; i < 8; ++i)
                #pragma unroll
                for (int j = 0; j < 8; ++j)
                    acc[i][j] += af[i] * wf[j];
        }
        if (hasNext) {
            #pragma unroll
            for (int p = 0; p < HQ; ++p) {
                const int r = ldRow + p * ROWSPP;
                #pragma unroll
                for (int q = 0; q < 4; ++q) {
                    An[(ldCol + q) * 128 + r] = (&pa[p].x)[q];
                    Wn[(ldCol + q) * 128 + r] = (&pw[p].x)[q];
                }
            }
            #pragma unroll
            for (int p = 0; p < HQ; ++p) {
                const int r = ldRow + (HQ + p) * ROWSPP;
                pa[p] = *reinterpret_cast<const float4*>(A + (size_t)(m0 + r) * K + kn + ldCol);
                const int wn = n0 + r;
                pw[p] = (wn < N)
                    ? *reinterpret_cast<const float4*>(W + (size_t)wn * K + kn + ldCol) : z4;
            }
        }
        #pragma unroll
        for (int kk = BK / 2; kk < BK; ++kk) {
            float af[8], wf[8];
            *reinterpret_cast<float4*>(&af[0]) = *reinterpret_cast<const float4*>(Ab + kk * 128 + ty * 8);
            *reinterpret_cast<float4*>(&af[4]) = *reinterpret_cast<const float4*>(Ab + kk * 128 + ty * 8 + 4);
            *reinterpret_cast<float4*>(&wf[0]) = *reinterpret_cast<const float4*>(Wb + kk * 128 + tx * 4);
            *reinterpret_cast<float4*>(&wf[4]) = *reinterpret_cast<const float4*>(Wb + kk * 128 + 64 + tx * 4);
            #pragma unroll
            for (int i = 0; i < 8; ++i)
                #pragma unroll
                for (int j = 0; j < 8; ++j)
                    acc[i][j] += af[i] * wf[j];
        }
        if (hasNext) {
            #pragma unroll
            for (int p = 0; p < HQ; ++p) {
                const int r = ldRow + (HQ + p) * ROWSPP;
                #pragma unroll
                for (int q = 0; q < 4; ++q) {
                    An[(ldCol + q) * 128 + r] = (&pa[p].x)[q];
                    Wn[(ldCol + q) * 128 + r] = (&pw[p].x)[q];
                }
            }
            __syncthreads();
        }
    }

    #pragma unroll
    for (int i = 0; i < 8; ++i) {
        const int m = m0 + ty * 8 + i;
        {
            const int n = n0 + tx * 4;
            if (n < N) {
                float4 v;
                v.x = acc[i][0] + bias[n + 0];
                v.y = acc[i][1] + bias[n + 1];
                v.z = acc[i][2] + bias[n + 2];
                v.w = acc[i][3] + bias[n + 3];
                *reinterpret_cast<float4*>(C + (size_t)m * N + n) = v;
            }
        }
        {
            const int n = n0 + 64 + tx * 4;
            if (n < N) {
                float4 v;
                v.x = acc[i][4] + bias[n + 0];
                v.y = acc[i][5] + bias[n + 1];
                v.z = acc[i][6] + bias[n + 2];
                v.w = acc[i][7] + bias[n + 3];
                *reinterpret_cast<float4*>(C + (size_t)m * N + n) = v;
            }
        }
    }
}

// ===========================================================================
// Plain LIF recurrence (layer 2), float4-vectorized.
// ===========================================================================
__global__ void lif_kernel4(const float4* __restrict__ cur,
                            float4* __restrict__ spk,
                            const float* __restrict__ beta_ptr, int BH4)
{
    const int idx = blockIdx.x * blockDim.x + threadIdx.x;
    if (idx >= BH4) return;
    const float beta = fminf(fmaxf(beta_ptr[0], 0.0f), 1.0f);
    float4 mem = make_float4(0.f, 0.f, 0.f, 0.f);
    float4 rst = make_float4(0.f, 0.f, 0.f, 0.f);
    #pragma unroll
    for (int t = 0; t < T_STEPS; ++t) {
        const float4 c = cur[(size_t)t * BH4 + idx];
        float4 s;
        mem.x = beta * mem.x + c.x - rst.x; s.x = (mem.x - 1.0f > 0.0f) ? 1.0f : 0.0f;
        mem.y = beta * mem.y + c.y - rst.y; s.y = (mem.y - 1.0f > 0.0f) ? 1.0f : 0.0f;
        mem.z = beta * mem.z + c.z - rst.z; s.z = (mem.z - 1.0f > 0.0f) ? 1.0f : 0.0f;
        mem.w = beta * mem.w + c.w - rst.w; s.w = (mem.w - 1.0f > 0.0f) ? 1.0f : 0.0f;
        spk[(size_t)t * BH4 + idx] = s;
        rst = s;
    }
}

__global__ __launch_bounds__(256)
void gemm3_kernel(const float* __restrict__ S2, const float* __restrict__ W3,
                  const float* __restrict__ b3, float* __restrict__ C3, int M)
{
    __shared__ float w3s[NOUT * HID];
    for (int i = threadIdx.x; i < NOUT * HID; i += 256) w3s[i] = W3[i];
    __syncthreads();

    const int warp = threadIdx.x >> 5;
    const int lane = threadIdx.x & 31;
    const int row  = blockIdx.x * 8 + warp;
    if (row >= M) return;

    const float* s = S2 + (size_t)row * HID;
    float sv[HID / 32];
    #pragma unroll
    for (int i = 0; i < HID / 32; ++i) sv[i] = s[lane + i * 32];

    float accv[NOUT];
    #pragma unroll
    for (int o = 0; o < NOUT; ++o) {
        float a = 0.0f;
        #pragma unroll
        for (int i = 0; i < HID / 32; ++i)
            a += sv[i] * w3s[o * HID + lane + i * 32];
        accv[o] = a;
    }
    #pragma unroll
    for (int o = 0; o < NOUT; ++o) {
        float v = accv[o];
        #pragma unroll
        for (int off = 16; off > 0; off >>= 1)
            v += __shfl_down_sync(0xffffffffu, v, off);
        if (lane == 0) C3[(size_t)row * NOUT + o] = v + b3[o];
    }
}

__global__ void lif3_kernel(const float* __restrict__ C3,
                            float* __restrict__ s3r, float* __restrict__ out,
                            const float* __restrict__ beta_ptr)
{
    const int idx = blockIdx.x * blockDim.x + threadIdx.x;
    if (idx >= BATCH * NOUT) return;
    const float beta = fminf(fmaxf(beta_ptr[0], 0.0f), 1.0f);
    float mem = 0.0f, rst = 0.0f, sum = 0.0f;
    #pragma unroll
    for (int t = 0; t < T_STEPS; ++t) {
        const float c = C3[(size_t)t * BATCH * NOUT + idx];
        mem = beta * mem + c - rst;
        const float s = (mem - 1.0f > 0.0f) ? 1.0f : 0.0f;
        s3r[(size_t)t * BATCH * NOUT + idx] = s;
        sum += s;
        rst = s;
    }
    out[idx] = sum;
}

// ===========================================================================
extern "C" void kernel_launch(void* const* d_in, const int* in_sizes, int n_in,
                              void* d_out, int out_size)
{
    const float* x     = (const float*)d_in[0];
    const float* W1    = (const float*)d_in[1];
    const float* b1    = (const float*)d_in[2];
    const float* W2    = (const float*)d_in[3];
    const float* b2    = (const float*)d_in[4];
    const float* W3    = (const float*)d_in[5];
    const float* b3    = (const float*)d_in[6];
    const float* beta1 = (const float*)d_in[7];
    const float* beta2 = (const float*)d_in[8];
    const float* beta3 = (const float*)d_in[9];

    float* out = (float*)d_out;
    float* s1r = out + (size_t)BATCH * NOUT;
    float* s2r = s1r + (size_t)M_ROWS * HID;
    float* s3r = s2r + (size_t)M_ROWS * HID;

    float *c1, *c2, *c3, *w2t;
    uint32_t* masks;
    cudaGetSymbolAddress((void**)&c1, g_c1);
    cudaGetSymbolAddress((void**)&c2, g_c2);
    cudaGetSymbolAddress((void**)&c3, g_c3);
    cudaGetSymbolAddress((void**)&w2t, g_w2t);
    cudaGetSymbolAddress((void**)&masks, g_masks);

    constexpr int SM16   = 4 * 16 * 128 * 4;                 // 32 KB
    constexpr int SMEMG2 = SBK * 128 * 4 + G2_MROWS * 16;    // 64 KB + 1 KB
    static bool attr_set = false;
    if (!attr_set) {
        cudaFuncSetAttribute(sgemm_nt<16>, cudaFuncAttributeMaxDynamicSharedMemorySize, SM16);
        cudaFuncSetAttribute(gemm2_sparse, cudaFuncAttributeMaxDynamicSharedMemorySize, SMEMG2);
        attr_set = true;
    }

    const int BH4 = BATCH * HID / 4;             // 102400
    const dim3 grid((HID + 127) / 128, M_ROWS / 128);

    // 0) W2 -> W2T
    {
        dim3 tg(HID / 32, HID / 32);
        transpose_w2<<<tg, dim3(32, 8)>>>(W2, w2t);
    }

    // 1) C1 = X @ W1^T + b1   (dense scalar SGEMM, K=784, BK=16)
    sgemm_nt<16><<<grid, 256, SM16>>>(x, W1, b1, c1, M_ROWS, HID, DIN);

    // 2) LIF1 -> s1r + spike masks
    lif1_mask<<<BH4 / 256, 256>>>((const float4*)c1, (float4*)s1r, masks, beta1);

    // 3) sparse GEMM2: C2 = S1 @ W2^T + b2 (mask-driven, 2-deep pipeline)
    {
        dim3 sg((HID + 127) / 128, M_ROWS / G2_MROWS);   // 7 x 400
        gemm2_sparse<<<sg, 256, SMEMG2>>>(masks, w2t, b2, c2);
    }

    // 4) LIF2 -> s2r
    lif_kernel4<<<(BH4 + 255) / 256, 256>>>((const float4*)c2, (float4*)s2r, beta2, BH4);

    // 5) C3 = S2 @ W3^T + b3
    gemm3_kernel<<<M_ROWS / 8, 256>>>(s2r, W3, b3, c3, M_ROWS);

    // 6) LIF3 + sum
    lif3_kernel<<<(BATCH * NOUT + 255) / 256, 256>>>(c3, s3r, out, beta3);
}

// round 15
// speedup vs baseline: 1.0255x; 1.0255x over previous
#include <cuda_runtime.h>
#include <cstdint>

// ---------------------------------------------------------------------------
// ActivityDecaySNN: 3-layer LIF SNN forward. T=50, B=512, 784->800->800->10.
// BITWISE CONSTRAINT: currents must reproduce the reference's ascending-k fp32
// FMA chain per element. GEMM1: scalar SIMT SGEMM (FFMA issue roofline).
// GEMM2: sparse ascending gather of W2T rows via 32-bit spike-mask words
// (64-bit walk disproven in R13: ALU-emulation doubled overhead). R14: 2-deep
// software pipeline within each word run; adds strictly ascending-k.
// (R14 retry: previous submission hit a container-infra failure, no data.)
// d_out: out[512*10] | s1r[50*512*800] | s2r[50*512*800] | s3r[50*512*10]
// ---------------------------------------------------------------------------

#define T_STEPS 50
#define BATCH   512
#define DIN     784
#define HID     800
#define NOUT    10
#define M_ROWS  (T_STEPS * BATCH)   // 25600
#define SBK     128                 // GEMM2 k-rows per tile
#define NT2     7                   // 6 full tiles + 1 of 32 rows
#define BH4F    (BATCH * HID / 4)   // 102400

__device__ float    g_c1[(size_t)M_ROWS * HID];
__device__ float    g_c2[(size_t)M_ROWS * HID];
__device__ float    g_c3[(size_t)M_ROWS * NOUT];
__device__ float    g_w2t[(size_t)HID * HID];
__device__ uint32_t g_masks[(size_t)M_ROWS * NT2 * 4];   // 2.87 MB

// ===========================================================================
// W2 transpose: W2T[k][n] = W2[n][k]. 32x32 tiles.
// ===========================================================================
__global__ void transpose_w2(const float* __restrict__ W, float* __restrict__ WT)
{
    __shared__ float t[32][33];
    const int bx = blockIdx.x * 32, by = blockIdx.y * 32;
    #pragma unroll
    for (int r = 0; r < 4; ++r)
        t[threadIdx.y + r * 8][threadIdx.x] =
            W[(size_t)(by + threadIdx.y + r * 8) * HID + bx + threadIdx.x];
    __syncthreads();
    #pragma unroll
    for (int r = 0; r < 4; ++r)
        WT[(size_t)(bx + threadIdx.y + r * 8) * HID + by + threadIdx.x] =
            t[threadIdx.x][threadIdx.y + r * 8];
}

// ===========================================================================
// LIF layer 1 + spike-mask emission (unchanged from R11).
// ===========================================================================
__global__ void lif1_mask(const float4* __restrict__ cur,
                          float4* __restrict__ spk,
                          uint32_t* __restrict__ masks,
                          const float* __restrict__ beta_ptr)
{
    const int idx = blockIdx.x * blockDim.x + threadIdx.x;   // [0, 102400)
    const int lane = threadIdx.x & 31;
    const int b    = idx / 200;
    const int h4   = idx % 200;
    const int hb4  = h4 & ~7;
    const int tile = hb4 >> 5;
    const int word = (hb4 >> 3) & 3;
    const bool wr  = ((lane & 7) == 0);
    const int sh   = 4 * (lane & 7);

    const float beta = fminf(fmaxf(beta_ptr[0], 0.0f), 1.0f);
    float4 mem = make_float4(0.f, 0.f, 0.f, 0.f);
    float4 rst = make_float4(0.f, 0.f, 0.f, 0.f);
    #pragma unroll
    for (int t = 0; t < T_STEPS; ++t) {
        const float4 c = cur[(size_t)t * BH4F + idx];
        float4 s;
        mem.x = beta * mem.x + c.x - rst.x; s.x = (mem.x - 1.0f > 0.0f) ? 1.0f : 0.0f;
        mem.y = beta * mem.y + c.y - rst.y; s.y = (mem.y - 1.0f > 0.0f) ? 1.0f : 0.0f;
        mem.z = beta * mem.z + c.z - rst.z; s.z = (mem.z - 1.0f > 0.0f) ? 1.0f : 0.0f;
        mem.w = beta * mem.w + c.w - rst.w; s.w = (mem.w - 1.0f > 0.0f) ? 1.0f : 0.0f;
        spk[(size_t)t * BH4F + idx] = s;
        rst = s;

        uint32_t nib = (s.x != 0.0f ? 1u : 0u) | (s.y != 0.0f ? 2u : 0u)
                     | (s.z != 0.0f ? 4u : 0u) | (s.w != 0.0f ? 8u : 0u);
        uint32_t wv = nib << sh;
        wv |= __shfl_xor_sync(0xffffffffu, wv, 1);
        wv |= __shfl_xor_sync(0xffffffffu, wv, 2);
        wv |= __shfl_xor_sync(0xffffffffu, wv, 4);
        if (wr) {
            const int m = t * BATCH + b;
            masks[((size_t)m * NT2 + tile) * 4 + word] = wv;
        }
    }
}

// ===========================================================================
// Sparse GEMM2: C2[m,n] = b2[n] + sum_{k active(m), ascending} W2T[k][n]
// Block: 64 m x 128 n; 8 warps, warp owns 8 m-rows. 3 blocks/SM (24 warps).
// W2T staged in 128-row k-tiles (64 KB); block's 64 mask uint4s staged too.
// Inner loop: 32-bit word runs, 2-deep pipelined ffs gather (two W-rows in
// flight). Adds execute in exactly ascending-k order -> bitwise identical.
// ===========================================================================
#define G2_MROWS 64

__global__ __launch_bounds__(256, 3)
void gemm2_sparse(const uint32_t* __restrict__ masks,
                  const float* __restrict__ WT,
                  const float* __restrict__ bias, float* __restrict__ C)
{
    extern __shared__ float wt[];            // SBK*128 floats + 64 uint4 masks
    uint4* wmask = reinterpret_cast<uint4*>(wt + SBK * 128);

    const int tid   = threadIdx.x;
    const int warp  = tid >> 5;
    const int lane  = tid & 31;
    const int n0    = blockIdx.x * 128;
    const int m0    = blockIdx.y * G2_MROWS;
    const int m0w   = m0 + warp * 8;
    const int lane4 = lane * 4;

    float acc[8][4];
    #pragma unroll
    for (int mi = 0; mi < 8; ++mi)
        #pragma unroll
        for (int j = 0; j < 4; ++j) acc[mi][j] = 0.0f;

#define ACCADD(V)                                                    \
    { acc[mi][0] += (V).x; acc[mi][1] += (V).y;                      \
      acc[mi][2] += (V).z; acc[mi][3] += (V).w; }

    #pragma unroll
    for (int t = 0; t < NT2; ++t) {
        const int rows   = (t < 6) ? SBK : 32;
        const int chunks = rows * 32;
        __syncthreads();   // protect previous tile before restage
        #pragma unroll
        for (int p = 0; p < 16; ++p) {
            const int i = tid + p * 256;
            if (i < chunks) {
                const int row = i >> 5, c4 = i & 31;
                const int gn  = n0 + c4 * 4;
                const float4 v = (gn < HID)
                    ? *reinterpret_cast<const float4*>(WT + (size_t)(t * SBK + row) * HID + gn)
                    : make_float4(0.f, 0.f, 0.f, 0.f);
                *reinterpret_cast<float4*>(&wt[row * 128 + c4 * 4]) = v;
            }
        }
        if (tid < G2_MROWS)
            wmask[tid] = __ldg(reinterpret_cast<const uint4*>(
                masks + ((size_t)(m0 + tid) * NT2 + t) * 4));
        __syncthreads();

        const int nwords = (t < 6) ? 4 : 1;
        #pragma unroll
        for (int mi = 0; mi < 8; ++mi) {
            const uint4 mv = wmask[warp * 8 + mi];   // broadcast LDS
            uint32_t mw[4] = {mv.x, mv.y, mv.z, mv.w};
            #pragma unroll
            for (int w = 0; w < 4; ++w) {
                if (w >= nwords) break;
                uint32_t bits = mw[w];
                if (!bits) continue;
                const float* wb = wt + (size_t)w * 32 * 128 + lane4;
                int k0 = __ffs(bits) - 1;
                bits &= bits - 1;
                float4 v0 = *reinterpret_cast<const float4*>(wb + k0 * 128);
                if (!bits) { ACCADD(v0); continue; }
                int k1 = __ffs(bits) - 1;
                bits &= bits - 1;
                float4 v1 = *reinterpret_cast<const float4*>(wb + k1 * 128);
                while (bits) {
                    const int k2 = __ffs(bits) - 1;
                    bits &= bits - 1;
                    const float4 v2 = *reinterpret_cast<const float4*>(wb + k2 * 128);
                    ACCADD(v0);
                    v0 = v1;
                    v1 = v2;
                }
                ACCADD(v0);
                ACCADD(v1);
            }
        }
    }
#undef ACCADD

    // ---- epilogue: bias + store ----
    const int gn = n0 + lane4;
    if (gn < HID) {
        const float4 b = *reinterpret_cast<const float4*>(bias + gn);
        #pragma unroll
        for (int mi = 0; mi < 8; ++mi) {
            float4 v;
            v.x = acc[mi][0] + b.x;
            v.y = acc[mi][1] + b.y;
            v.z = acc[mi][2] + b.z;
            v.w = acc[mi][3] + b.w;
            *reinterpret_cast<float4*>(C + (size_t)(m0w + mi) * HID + gn) = v;
        }
    }
}

// ===========================================================================
// Dense SIMT SGEMM (NT) for layer 1 — R4/R7 version (bitwise, at FFMA floor).
// ===========================================================================
template<int BK>
__global__ __launch_bounds__(256, 2)
void sgemm_nt(const float* __restrict__ A, const float* __restrict__ W,
              const float* __restrict__ bias, float* __restrict__ C,
              int M, int N, int K)
{
    constexpr int QPR    = BK / 4;
    constexpr int ROWSPP = 256 / QPR;
    constexpr int NQ     = BK / 8;
    constexpr int HQ     = NQ / 2;

    extern __shared__ float sm[];
    float* As = sm;
    float* Ws = sm + 2 * BK * 128;

    const int tid = threadIdx.x;
    const int tx  = tid & 15;
    const int ty  = tid >> 4;
    const int m0  = blockIdx.y * 128;
    const int n0  = blockIdx.x * 128;

    const int ldCol = (tid % QPR) * 4;
    const int ldRow = tid / QPR;

    float acc[8][8];
    #pragma unroll
    for (int i = 0; i < 8; ++i)
        #pragma unroll
        for (int j = 0; j < 8; ++j) acc[i][j] = 0.0f;

    const int numTiles = K / BK;
    const float4 z4 = make_float4(0.f, 0.f, 0.f, 0.f);

    #pragma unroll
    for (int p = 0; p < NQ; ++p) {
        const int r  = ldRow + p * ROWSPP;
        const float4 av = *reinterpret_cast<const float4*>(A + (size_t)(m0 + r) * K + ldCol);
        const int wn = n0 + r;
        const float4 wv = (wn < N)
            ? *reinterpret_cast<const float4*>(W + (size_t)wn * K + ldCol) : z4;
        #pragma unroll
        for (int q = 0; q < 4; ++q) {
            As[(ldCol + q) * 128 + r] = (&av.x)[q];
            Ws[(ldCol + q) * 128 + r] = (&wv.x)[q];
        }
    }
    __syncthreads();

    for (int t = 0; t < numTiles; ++t) {
        const int  buf     = t & 1;
        const int  nb      = buf ^ 1;
        const bool hasNext = (t + 1 < numTiles);
        const int  kn      = (t + 1) * BK;

        float* Ab = As + buf * BK * 128;
        float* Wb = Ws + buf * BK * 128;
        float* An = As + nb * BK * 128;
        float* Wn = Ws + nb * BK * 128;

        float4 pa[HQ], pw[HQ];

        if (hasNext) {
            #pragma unroll
            for (int p = 0; p < HQ; ++p) {
                const int r = ldRow + p * ROWSPP;
                pa[p] = *reinterpret_cast<const float4*>(A + (size_t)(m0 + r) * K + kn + ldCol);
                const int wn = n0 + r;
                pw[p] = (wn < N)
                    ? *reinterpret_cast<const float4*>(W + (size_t)wn * K + kn + ldCol) : z4;
            }
        }
        #pragma unroll
        for (int kk = 0; kk < BK / 2; ++kk) {
            float af[8], wf[8];
            *reinterpret_cast<float4*>(&af[0]) = *reinterpret_cast<const float4*>(Ab + kk * 128 + ty * 8);
            *reinterpret_cast<float4*>(&af[4]) = *reinterpret_cast<const float4*>(Ab + kk * 128 + ty * 8 + 4);
            *reinterpret_cast<float4*>(&wf[0]) = *reinterpret_cast<const float4*>(Wb + kk * 128 + tx * 4);
            *reinterpret_cast<float4*>(&wf[4]) = *reinterpret_cast<const float4*>(Wb + kk * 128 + 64 + tx * 4);
            #pragma unroll
            for (int i = 0; i < 8; ++i)
                #pragma unroll
                for (int j = 0; j < 8; ++j)
                    acc[i][j] += af[i] * wf[j];
        }
        if (hasNext) {
            #pragma unroll
            for (int p = 0; p < HQ; ++p) {
                const int r = ldRow + p * ROWSPP;
                #pragma unroll
                for (int q = 0; q < 4; ++q) {
                    An[(ldCol + q) * 128 + r] = (&pa[p].x)[q];
                    Wn[(ldCol + q) * 128 + r] = (&pw[p].x)[q];
                }
            }
            #pragma unroll
            for (int p = 0; p < HQ; ++p) {
                const int r = ldRow + (HQ + p) * ROWSPP;
                pa[p] = *reinterpret_cast<const float4*>(A + (size_t)(m0 + r) * K + kn + ldCol);
                const int wn = n0 + r;
                pw[p] = (wn < N)
                    ? *reinterpret_cast<const float4*>(W + (size_t)wn * K + kn + ldCol) : z4;
            }
        }
        #pragma unroll
        for (int kk = BK / 2; kk < BK; ++kk) {
            float af[8], wf[8];
            *reinterpret_cast<float4*>(&af[0]) = *reinterpret_cast<const float4*>(Ab + kk * 128 + ty * 8);
            *reinterpret_cast<float4*>(&af[4]) = *reinterpret_cast<const float4*>(Ab + kk * 128 + ty * 8 + 4);
            *reinterpret_cast<float4*>(&wf[0]) = *reinterpret_cast<const float4*>(Wb + kk * 128 + tx * 4);
            *reinterpret_cast<float4*>(&wf[4]) = *reinterpret_cast<const float4*>(Wb + kk * 128 + 64 + tx * 4);
            #pragma unroll
            for (int i = 0; i < 8; ++i)
                #pragma unroll
                for (int j = 0; j < 8; ++j)
                    acc[i][j] += af[i] * wf[j];
        }
        if (hasNext) {
            #pragma unroll
            for (int p = 0; p < HQ; ++p) {
                const int r = ldRow + (HQ + p) * ROWSPP;
                #pragma unroll
                for (int q = 0; q < 4; ++q) {
                    An[(ldCol + q) * 128 + r] = (&pa[p].x)[q];
                    Wn[(ldCol + q) * 128 + r] = (&pw[p].x)[q];
                }
            }
            __syncthreads();
        }
    }

    #pragma unroll
    for (int i = 0; i < 8; ++i) {
        const int m = m0 + ty * 8 + i;
        {
            const int n = n0 + tx * 4;
            if (n < N) {
                float4 v;
                v.x = acc[i][0] + bias[n + 0];
                v.y = acc[i][1] + bias[n + 1];
                v.z = acc[i][2] + bias[n + 2];
                v.w = acc[i][3] + bias[n + 3];
                *reinterpret_cast<float4*>(C + (size_t)m * N + n) = v;
            }
        }
        {
            const int n = n0 + 64 + tx * 4;
            if (n < N) {
                float4 v;
                v.x = acc[i][4] + bias[n + 0];
                v.y = acc[i][5] + bias[n + 1];
                v.z = acc[i][6] + bias[n + 2];
                v.w = acc[i][7] + bias[n + 3];
                *reinterpret_cast<float4*>(C + (size_t)m * N + n) = v;
            }
        }
    }
}

// ===========================================================================
// Plain LIF recurrence (layer 2), float4-vectorized.
// ===========================================================================
__global__ void lif_kernel4(const float4* __restrict__ cur,
                            float4* __restrict__ spk,
                            const float* __restrict__ beta_ptr, int BH4)
{
    const int idx = blockIdx.x * blockDim.x + threadIdx.x;
    if (idx >= BH4) return;
    const float beta = fminf(fmaxf(beta_ptr[0], 0.0f), 1.0f);
    float4 mem = make_float4(0.f, 0.f, 0.f, 0.f);
    float4 rst = make_float4(0.f, 0.f, 0.f, 0.f);
    #pragma unroll
    for (int t = 0; t < T_STEPS; ++t) {
        const float4 c = cur[(size_t)t * BH4 + idx];
        float4 s;
        mem.x = beta * mem.x + c.x - rst.x; s.x = (mem.x - 1.0f > 0.0f) ? 1.0f : 0.0f;
        mem.y = beta * mem.y + c.y - rst.y; s.y = (mem.y - 1.0f > 0.0f) ? 1.0f : 0.0f;
        mem.z = beta * mem.z + c.z - rst.z; s.z = (mem.z - 1.0f > 0.0f) ? 1.0f : 0.0f;
        mem.w = beta * mem.w + c.w - rst.w; s.w = (mem.w - 1.0f > 0.0f) ? 1.0f : 0.0f;
        spk[(size_t)t * BH4 + idx] = s;
        rst = s;
    }
}

__global__ __launch_bounds__(256)
void gemm3_kernel(const float* __restrict__ S2, const float* __restrict__ W3,
                  const float* __restrict__ b3, float* __restrict__ C3, int M)
{
    __shared__ float w3s[NOUT * HID];
    for (int i = threadIdx.x; i < NOUT * HID; i += 256) w3s[i] = W3[i];
    __syncthreads();

    const int warp = threadIdx.x >> 5;
    const int lane = threadIdx.x & 31;
    const int row  = blockIdx.x * 8 + warp;
    if (row >= M) return;

    const float* s = S2 + (size_t)row * HID;
    float sv[HID / 32];
    #pragma unroll
    for (int i = 0; i < HID / 32; ++i) sv[i] = s[lane + i * 32];

    float accv[NOUT];
    #pragma unroll
    for (int o = 0; o < NOUT; ++o) {
        float a = 0.0f;
        #pragma unroll
        for (int i = 0; i < HID / 32; ++i)
            a += sv[i] * w3s[o * HID + lane + i * 32];
        accv[o] = a;
    }
    #pragma unroll
    for (int o = 0; o < NOUT; ++o) {
        float v = accv[o];
        #pragma unroll
        for (int off = 16; off > 0; off >>= 1)
            v += __shfl_down_sync(0xffffffffu, v, off);
        if (lane == 0) C3[(size_t)row * NOUT + o] = v + b3[o];
    }
}

__global__ void lif3_kernel(const float* __restrict__ C3,
                            float* __restrict__ s3r, float* __restrict__ out,
                            const float* __restrict__ beta_ptr)
{
    const int idx = blockIdx.x * blockDim.x + threadIdx.x;
    if (idx >= BATCH * NOUT) return;
    const float beta = fminf(fmaxf(beta_ptr[0], 0.0f), 1.0f);
    float mem = 0.0f, rst = 0.0f, sum = 0.0f;
    #pragma unroll
    for (int t = 0; t < T_STEPS; ++t) {
        const float c = C3[(size_t)t * BATCH * NOUT + idx];
        mem = beta * mem + c - rst;
        const float s = (mem - 1.0f > 0.0f) ? 1.0f : 0.0f;
        s3r[(size_t)t * BATCH * NOUT + idx] = s;
        sum += s;
        rst = s;
    }
    out[idx] = sum;
}

// ===========================================================================
extern "C" void kernel_launch(void* const* d_in, const int* in_sizes, int n_in,
                              void* d_out, int out_size)
{
    const float* x     = (const float*)d_in[0];
    const float* W1    = (const float*)d_in[1];
    const float* b1    = (const float*)d_in[2];
    const float* W2    = (const float*)d_in[3];
    const float* b2    = (const float*)d_in[4];
    const float* W3    = (const float*)d_in[5];
    const float* b3    = (const float*)d_in[6];
    const float* beta1 = (const float*)d_in[7];
    const float* beta2 = (const float*)d_in[8];
    const float* beta3 = (const float*)d_in[9];

    float* out = (float*)d_out;
    float* s1r = out + (size_t)BATCH * NOUT;
    float* s2r = s1r + (size_t)M_ROWS * HID;
    float* s3r = s2r + (size_t)M_ROWS * HID;

    float *c1, *c2, *c3, *w2t;
    uint32_t* masks;
    cudaGetSymbolAddress((void**)&c1, g_c1);
    cudaGetSymbolAddress((void**)&c2, g_c2);
    cudaGetSymbolAddress((void**)&c3, g_c3);
    cudaGetSymbolAddress((void**)&w2t, g_w2t);
    cudaGetSymbolAddress((void**)&masks, g_masks);

    constexpr int SM16   = 4 * 16 * 128 * 4;                 // 32 KB
    constexpr int SMEMG2 = SBK * 128 * 4 + G2_MROWS * 16;    // 64 KB + 1 KB
    static bool attr_set = false;
    if (!attr_set) {
        cudaFuncSetAttribute(sgemm_nt<16>, cudaFuncAttributeMaxDynamicSharedMemorySize, SM16);
        cudaFuncSetAttribute(gemm2_sparse, cudaFuncAttributeMaxDynamicSharedMemorySize, SMEMG2);
        attr_set = true;
    }

    const int BH4 = BATCH * HID / 4;             // 102400
    const dim3 grid((HID + 127) / 128, M_ROWS / 128);

    // 0) W2 -> W2T
    {
        dim3 tg(HID / 32, HID / 32);
        transpose_w2<<<tg, dim3(32, 8)>>>(W2, w2t);
    }

    // 1) C1 = X @ W1^T + b1   (dense scalar SGEMM, K=784, BK=16)
    sgemm_nt<16><<<grid, 256, SM16>>>(x, W1, b1, c1, M_ROWS, HID, DIN);

    // 2) LIF1 -> s1r + spike masks
    lif1_mask<<<BH4 / 256, 256>>>((const float4*)c1, (float4*)s1r, masks, beta1);

    // 3) sparse GEMM2: C2 = S1 @ W2^T + b2 (32-bit words, 2-deep pipeline)
    {
        dim3 sg((HID + 127) / 128, M_ROWS / G2_MROWS);   // 7 x 400
        gemm2_sparse<<<sg, 256, SMEMG2>>>(masks, w2t, b2, c2);
    }

    // 4) LIF2 -> s2r
    lif_kernel4<<<(BH4 + 255) / 256, 256>>>((const float4*)c2, (float4*)s2r, beta2, BH4);

    // 5) C3 = S2 @ W3^T + b3
    gemm3_kernel<<<M_ROWS / 8, 256>>>(s2r, W3, b3, c3, M_ROWS);

    // 6) LIF3 + sum
    lif3_kernel<<<(BATCH * NOUT + 255) / 256, 256>>>(c3, s3r, out, beta3);
}

// round 16
// speedup vs baseline: 1.0751x; 1.0484x over previous
#include <cuda_runtime.h>
#include <cstdint>

// ---------------------------------------------------------------------------
// ActivityDecaySNN: 3-layer LIF SNN forward. T=50, B=512, 784->800->800->10.
// BITWISE CONSTRAINT: currents must reproduce the reference's ascending-k fp32
// FMA chain per element. GEMM1: scalar SIMT SGEMM (FFMA issue roofline).
// GEMM2: sparse ascending gather of W2T rows via 32-bit spike-mask words,
// R12-style 1-deep walk (2-deep and 64-bit variants both measured slower).
// R16: SBK 128->96 => 4 blocks/SM (32 warps) for latency hiding; flat 25-word
// mask layout (tile t uses words 3t..3t+2). Adds strictly ascending-k.
// d_out: out[512*10] | s1r[50*512*800] | s2r[50*512*800] | s3r[50*512*10]
// ---------------------------------------------------------------------------

#define T_STEPS 50
#define BATCH   512
#define DIN     784
#define HID     800
#define NOUT    10
#define M_ROWS  (T_STEPS * BATCH)   // 25600
#define SBK     96                  // GEMM2 k-rows per tile
#define NTT     9                   // 8 full tiles + 1 of 32 rows
#define MWPAD   28                  // mask words per row (25 used, padded)
#define BH4F    (BATCH * HID / 4)   // 102400

__device__ float    g_c1[(size_t)M_ROWS * HID];
__device__ float    g_c2[(size_t)M_ROWS * HID];
__device__ float    g_c3[(size_t)M_ROWS * NOUT];
__device__ float    g_w2t[(size_t)HID * HID];
__device__ uint32_t g_masks[(size_t)M_ROWS * MWPAD];   // 2.87 MB

// ===========================================================================
// W2 transpose: W2T[k][n] = W2[n][k]. 32x32 tiles.
// ===========================================================================
__global__ void transpose_w2(const float* __restrict__ W, float* __restrict__ WT)
{
    __shared__ float t[32][33];
    const int bx = blockIdx.x * 32, by = blockIdx.y * 32;
    #pragma unroll
    for (int r = 0; r < 4; ++r)
        t[threadIdx.y + r * 8][threadIdx.x] =
            W[(size_t)(by + threadIdx.y + r * 8) * HID + bx + threadIdx.x];
    __syncthreads();
    #pragma unroll
    for (int r = 0; r < 4; ++r)
        WT[(size_t)(bx + threadIdx.y + r * 8) * HID + by + threadIdx.x] =
            t[threadIdx.x][threadIdx.y + r * 8];
}

// ===========================================================================
// LIF layer 1 + spike-mask emission (flat word layout: word = h/32, 0..24).
// ===========================================================================
__global__ void lif1_mask(const float4* __restrict__ cur,
                          float4* __restrict__ spk,
                          uint32_t* __restrict__ masks,
                          const float* __restrict__ beta_ptr)
{
    const int idx = blockIdx.x * blockDim.x + threadIdx.x;   // [0, 102400)
    const int lane = threadIdx.x & 31;
    const int b    = idx / 200;
    const int h4   = idx % 200;
    const int hb4  = h4 & ~7;
    const int word = hb4 >> 3;                // flat word index 0..24
    const bool wr  = ((lane & 7) == 0);
    const int sh   = 4 * (lane & 7);

    const float beta = fminf(fmaxf(beta_ptr[0], 0.0f), 1.0f);
    float4 mem = make_float4(0.f, 0.f, 0.f, 0.f);
    float4 rst = make_float4(0.f, 0.f, 0.f, 0.f);
    #pragma unroll
    for (int t = 0; t < T_STEPS; ++t) {
        const float4 c = cur[(size_t)t * BH4F + idx];
        float4 s;
        mem.x = beta * mem.x + c.x - rst.x; s.x = (mem.x - 1.0f > 0.0f) ? 1.0f : 0.0f;
        mem.y = beta * mem.y + c.y - rst.y; s.y = (mem.y - 1.0f > 0.0f) ? 1.0f : 0.0f;
        mem.z = beta * mem.z + c.z - rst.z; s.z = (mem.z - 1.0f > 0.0f) ? 1.0f : 0.0f;
        mem.w = beta * mem.w + c.w - rst.w; s.w = (mem.w - 1.0f > 0.0f) ? 1.0f : 0.0f;
        spk[(size_t)t * BH4F + idx] = s;
        rst = s;

        uint32_t nib = (s.x != 0.0f ? 1u : 0u) | (s.y != 0.0f ? 2u : 0u)
                     | (s.z != 0.0f ? 4u : 0u) | (s.w != 0.0f ? 8u : 0u);
        uint32_t wv = nib << sh;
        wv |= __shfl_xor_sync(0xffffffffu, wv, 1);
        wv |= __shfl_xor_sync(0xffffffffu, wv, 2);
        wv |= __shfl_xor_sync(0xffffffffu, wv, 4);
        if (wr) {
            const int m = t * BATCH + b;
            masks[(size_t)m * MWPAD + word] = wv;
        }
    }
}

// ===========================================================================
// Sparse GEMM2: C2[m,n] = b2[n] + sum_{k active(m), ascending} W2T[k][n]
// Block: 64 m x 128 n; 8 warps, warp owns 8 m-rows. 4 blocks/SM (32 warps).
// W2T staged in 96-row k-tiles (48 KB); block's masks (3 words/row) staged.
// Inner loop: R12-style 1-deep pipelined ffs walk over 32-bit words.
// ===========================================================================
#define G2_MROWS 64

__global__ __launch_bounds__(256, 4)
void gemm2_sparse(const uint32_t* __restrict__ masks,
                  const float* __restrict__ WT,
                  const float* __restrict__ bias, float* __restrict__ C)
{
    extern __shared__ float wt[];            // SBK*128 floats + 64*3 mask words
    uint32_t* smask = reinterpret_cast<uint32_t*>(wt + SBK * 128);

    const int tid   = threadIdx.x;
    const int warp  = tid >> 5;
    const int lane  = tid & 31;
    const int n0    = blockIdx.x * 128;
    const int m0    = blockIdx.y * G2_MROWS;
    const int m0w   = m0 + warp * 8;
    const int lane4 = lane * 4;

    float acc[8][4];
    #pragma unroll
    for (int mi = 0; mi < 8; ++mi)
        #pragma unroll
        for (int j = 0; j < 4; ++j) acc[mi][j] = 0.0f;

#define ACCADD(V)                                                    \
    { acc[mi][0] += (V).x; acc[mi][1] += (V).y;                      \
      acc[mi][2] += (V).z; acc[mi][3] += (V).w; }

    #pragma unroll
    for (int t = 0; t < NTT; ++t) {
        const int rows   = (t < 8) ? SBK : 32;
        const int nwords = (t < 8) ? 3 : 1;
        const int chunks = rows * 32;
        __syncthreads();   // protect previous tile before restage
        #pragma unroll
        for (int p = 0; p < 12; ++p) {
            const int i = tid + p * 256;
            if (i < chunks) {
                const int row = i >> 5, c4 = i & 31;
                const int gn  = n0 + c4 * 4;
                const float4 v = (gn < HID)
                    ? *reinterpret_cast<const float4*>(WT + (size_t)(t * SBK + row) * HID + gn)
                    : make_float4(0.f, 0.f, 0.f, 0.f);
                *reinterpret_cast<float4*>(&wt[row * 128 + c4 * 4]) = v;
            }
        }
        if (tid < G2_MROWS * nwords) {
            const int row = tid / nwords;
            const int j   = tid - row * nwords;
            smask[row * 3 + j] = __ldg(masks + (size_t)(m0 + row) * MWPAD + 3 * t + j);
        }
        __syncthreads();

        #pragma unroll
        for (int mi = 0; mi < 8; ++mi) {
            const int mb = (warp * 8 + mi) * 3;
            #pragma unroll
            for (int w = 0; w < 3; ++w) {
                if (w >= nwords) break;
                uint32_t bits = smask[mb + w];    // broadcast LDS
                if (!bits) continue;
                const float* wb = wt + (size_t)w * 32 * 128 + lane4;
                int k = __ffs(bits) - 1;
                bits &= bits - 1;
                float4 wv = *reinterpret_cast<const float4*>(wb + k * 128);
                while (bits) {
                    const int k2 = __ffs(bits) - 1;
                    bits &= bits - 1;
                    const float4 nv = *reinterpret_cast<const float4*>(wb + k2 * 128);
                    ACCADD(wv);
                    wv = nv;
                }
                ACCADD(wv);
            }
        }
    }
#undef ACCADD

    // ---- epilogue: bias + store ----
    const int gn = n0 + lane4;
    if (gn < HID) {
        const float4 b = *reinterpret_cast<const float4*>(bias + gn);
        #pragma unroll
        for (int mi = 0; mi < 8; ++mi) {
            float4 v;
            v.x = acc[mi][0] + b.x;
            v.y = acc[mi][1] + b.y;
            v.z = acc[mi][2] + b.z;
            v.w = acc[mi][3] + b.w;
            *reinterpret_cast<float4*>(C + (size_t)(m0w + mi) * HID + gn) = v;
        }
    }
}

// ===========================================================================
// Dense SIMT SGEMM (NT) for layer 1 — R4/R7 version (bitwise, at FFMA floor).
// ===========================================================================
template<int BK>
__global__ __launch_bounds__(256, 2)
void sgemm_nt(const float* __restrict__ A, const float* __restrict__ W,
              const float* __restrict__ bias, float* __restrict__ C,
              int M, int N, int K)
{
    constexpr int QPR    = BK / 4;
    constexpr int ROWSPP = 256 / QPR;
    constexpr int NQ     = BK / 8;
    constexpr int HQ     = NQ / 2;

    extern __shared__ float sm[];
    float* As = sm;
    float* Ws = sm + 2 * BK * 128;

    const int tid = threadIdx.x;
    const int tx  = tid & 15;
    const int ty  = tid >> 4;
    const int m0  = blockIdx.y * 128;
    const int n0  = blockIdx.x * 128;

    const int ldCol = (tid % QPR) * 4;
    const int ldRow = tid / QPR;

    float acc[8][8];
    #pragma unroll
    for (int i = 0; i < 8; ++i)
        #pragma unroll
        for (int j = 0; j < 8; ++j) acc[i][j] = 0.0f;

    const int numTiles = K / BK;
    const float4 z4 = make_float4(0.f, 0.f, 0.f, 0.f);

    #pragma unroll
    for (int p = 0; p < NQ; ++p) {
        const int r  = ldRow + p * ROWSPP;
        const float4 av = *reinterpret_cast<const float4*>(A + (size_t)(m0 + r) * K + ldCol);
        const int wn = n0 + r;
        const float4 wv = (wn < N)
            ? *reinterpret_cast<const float4*>(W + (size_t)wn * K + ldCol) : z4;
        #pragma unroll
        for (int q = 0; q < 4; ++q) {
            As[(ldCol + q) * 128 + r] = (&av.x)[q];
            Ws[(ldCol + q) * 128 + r] = (&wv.x)[q];
        }
    }
    __syncthreads();

    for (int t = 0; t < numTiles; ++t) {
        const int  buf     = t & 1;
        const int  nb      = buf ^ 1;
        const bool hasNext = (t + 1 < numTiles);
        const int  kn      = (t + 1) * BK;

        float* Ab = As + buf * BK * 128;
        float* Wb = Ws + buf * BK * 128;
        float* An = As + nb * BK * 128;
        float* Wn = Ws + nb * BK * 128;

        float4 pa[HQ], pw[HQ];

        if (hasNext) {
            #pragma unroll
            for (int p = 0; p < HQ; ++p) {
                const int r = ldRow + p * ROWSPP;
                pa[p] = *reinterpret_cast<const float4*>(A + (size_t)(m0 + r) * K + kn + ldCol);
                const int wn = n0 + r;
                pw[p] = (wn < N)
                    ? *reinterpret_cast<const float4*>(W + (size_t)wn * K + kn + ldCol) : z4;
            }
        }
        #pragma unroll
        for (int kk = 0; kk < BK / 2; ++kk) {
            float af[8], wf[8];
            *reinterpret_cast<float4*>(&af[0]) = *reinterpret_cast<const float4*>(Ab + kk * 128 + ty * 8);
            *reinterpret_cast<float4*>(&af[4]) = *reinterpret_cast<const float4*>(Ab + kk * 128 + ty * 8 + 4);
            *reinterpret_cast<float4*>(&wf[0]) = *reinterpret_cast<const float4*>(Wb + kk * 128 + tx * 4);
            *reinterpret_cast<float4*>(&wf[4]) = *reinterpret_cast<const float4*>(Wb + kk * 128 + 64 + tx * 4);
            #pragma unroll
            for (int i = 0; i < 8; ++i)
                #pragma unroll
                for (int j = 0; j < 8; ++j)
                    acc[i][j] += af[i] * wf[j];
        }
        if (hasNext) {
            #pragma unroll
            for (int p = 0; p < HQ; ++p) {
                const int r = ldRow + p * ROWSPP;
                #pragma unroll
                for (int q = 0; q < 4; ++q) {
                    An[(ldCol + q) * 128 + r] = (&pa[p].x)[q];
                    Wn[(ldCol + q) * 128 + r] = (&pw[p].x)[q];
                }
            }
            #pragma unroll
            for (int p = 0; p < HQ; ++p) {
                const int r = ldRow + (HQ + p) * ROWSPP;
                pa[p] = *reinterpret_cast<const float4*>(A + (size_t)(m0 + r) * K + kn + ldCol);
                const int wn = n0 + r;
                pw[p] = (wn < N)
                    ? *reinterpret_cast<const float4*>(W + (size_t)wn * K + kn + ldCol) : z4;
            }
        }
        #pragma unroll
        for (int kk = BK / 2; kk < BK; ++kk) {
            float af[8], wf[8];
            *reinterpret_cast<float4*>(&af[0]) = *reinterpret_cast<const float4*>(Ab + kk * 128 + ty * 8);
            *reinterpret_cast<float4*>(&af[4]) = *reinterpret_cast<const float4*>(Ab + kk * 128 + ty * 8 + 4);
            *reinterpret_cast<float4*>(&wf[0]) = *reinterpret_cast<const float4*>(Wb + kk * 128 + tx * 4);
            *reinterpret_cast<float4*>(&wf[4]) = *reinterpret_cast<const float4*>(Wb + kk * 128 + 64 + tx * 4);
            #pragma unroll
            for (int i = 0; i < 8; ++i)
                #pragma unroll
                for (int j = 0; j < 8; ++j)
                    acc[i][j] += af[i] * wf[j];
        }
        if (hasNext) {
            #pragma unroll
            for (int p = 0; p < HQ; ++p) {
                const int r = ldRow + (HQ + p) * ROWSPP;
                #pragma unroll
                for (int q = 0; q < 4; ++q) {
                    An[(ldCol + q) * 128 + r] = (&pa[p].x)[q];
                    Wn[(ldCol + q) * 128 + r] = (&pw[p].x)[q];
                }
            }
            __syncthreads();
        }
    }

    #pragma unroll
    for (int i = 0; i < 8; ++i) {
        const int m = m0 + ty * 8 + i;
        {
            const int n = n0 + tx * 4;
            if (n < N) {
                float4 v;
                v.x = acc[i][0] + bias[n + 0];
                v.y = acc[i][1] + bias[n + 1];
                v.z = acc[i][2] + bias[n + 2];
                v.w = acc[i][3] + bias[n + 3];
                *reinterpret_cast<float4*>(C + (size_t)m * N + n) = v;
            }
        }
        {
            const int n = n0 + 64 + tx * 4;
            if (n < N) {
                float4 v;
                v.x = acc[i][4] + bias[n + 0];
                v.y = acc[i][5] + bias[n + 1];
                v.z = acc[i][6] + bias[n + 2];
                v.w = acc[i][7] + bias[n + 3];
                *reinterpret_cast<float4*>(C + (size_t)m * N + n) = v;
            }
        }
    }
}

// ===========================================================================
// Plain LIF recurrence (layer 2), float4-vectorized.
// ===========================================================================
__global__ void lif_kernel4(const float4* __restrict__ cur,
                            float4* __restrict__ spk,
                            const float* __restrict__ beta_ptr, int BH4)
{
    const int idx = blockIdx.x * blockDim.x + threadIdx.x;
    if (idx >= BH4) return;
    const float beta = fminf(fmaxf(beta_ptr[0], 0.0f), 1.0f);
    float4 mem = make_float4(0.f, 0.f, 0.f, 0.f);
    float4 rst = make_float4(0.f, 0.f, 0.f, 0.f);
    #pragma unroll
    for (int t = 0; t < T_STEPS; ++t) {
        const float4 c = cur[(size_t)t * BH4 + idx];
        float4 s;
        mem.x = beta * mem.x + c.x - rst.x; s.x = (mem.x - 1.0f > 0.0f) ? 1.0f : 0.0f;
        mem.y = beta * mem.y + c.y - rst.y; s.y = (mem.y - 1.0f > 0.0f) ? 1.0f : 0.0f;
        mem.z = beta * mem.z + c.z - rst.z; s.z = (mem.z - 1.0f > 0.0f) ? 1.0f : 0.0f;
        mem.w = beta * mem.w + c.w - rst.w; s.w = (mem.w - 1.0f > 0.0f) ? 1.0f : 0.0f;
        spk[(size_t)t * BH4 + idx] = s;
        rst = s;
    }
}

__global__ __launch_bounds__(256)
void gemm3_kernel(const float* __restrict__ S2, const float* __restrict__ W3,
                  const float* __restrict__ b3, float* __restrict__ C3, int M)
{
    __shared__ float w3s[NOUT * HID];
    for (int i = threadIdx.x; i < NOUT * HID; i += 256) w3s[i] = W3[i];
    __syncthreads();

    const int warp = threadIdx.x >> 5;
    const int lane = threadIdx.x & 31;
    const int row  = blockIdx.x * 8 + warp;
    if (row >= M) return;

    const float* s = S2 + (size_t)row * HID;
    float sv[HID / 32];
    #pragma unroll
    for (int i = 0; i < HID / 32; ++i) sv[i] = s[lane + i * 32];

    float accv[NOUT];
    #pragma unroll
    for (int o = 0; o < NOUT; ++o) {
        float a = 0.0f;
        #pragma unroll
        for (int i = 0; i < HID / 32; ++i)
            a += sv[i] * w3s[o * HID + lane + i * 32];
        accv[o] = a;
    }
    #pragma unroll
    for (int o = 0; o < NOUT; ++o) {
        float v = accv[o];
        #pragma unroll
        for (int off = 16; off > 0; off >>= 1)
            v += __shfl_down_sync(0xffffffffu, v, off);
        if (lane == 0) C3[(size_t)row * NOUT + o] = v + b3[o];
    }
}

__global__ void lif3_kernel(const float* __restrict__ C3,
                            float* __restrict__ s3r, float* __restrict__ out,
                            const float* __restrict__ beta_ptr)
{
    const int idx = blockIdx.x * blockDim.x + threadIdx.x;
    if (idx >= BATCH * NOUT) return;
    const float beta = fminf(fmaxf(beta_ptr[0], 0.0f), 1.0f);
    float mem = 0.0f, rst = 0.0f, sum = 0.0f;
    #pragma unroll
    for (int t = 0; t < T_STEPS; ++t) {
        const float c = C3[(size_t)t * BATCH * NOUT + idx];
        mem = beta * mem + c - rst;
        const float s = (mem - 1.0f > 0.0f) ? 1.0f : 0.0f;
        s3r[(size_t)t * BATCH * NOUT + idx] = s;
        sum += s;
        rst = s;
    }
    out[idx] = sum;
}

// ===========================================================================
extern "C" void kernel_launch(void* const* d_in, const int* in_sizes, int n_in,
                              void* d_out, int out_size)
{
    const float* x     = (const float*)d_in[0];
    const float* W1    = (const float*)d_in[1];
    const float* b1    = (const float*)d_in[2];
    const float* W2    = (const float*)d_in[3];
    const float* b2    = (const float*)d_in[4];
    const float* W3    = (const float*)d_in[5];
    const float* b3    = (const float*)d_in[6];
    const float* beta1 = (const float*)d_in[7];
    const float* beta2 = (const float*)d_in[8];
    const float* beta3 = (const float*)d_in[9];

    float* out = (float*)d_out;
    float* s1r = out + (size_t)BATCH * NOUT;
    float* s2r = s1r + (size_t)M_ROWS * HID;
    float* s3r = s2r + (size_t)M_ROWS * HID;

    float *c1, *c2, *c3, *w2t;
    uint32_t* masks;
    cudaGetSymbolAddress((void**)&c1, g_c1);
    cudaGetSymbolAddress((void**)&c2, g_c2);
    cudaGetSymbolAddress((void**)&c3, g_c3);
    cudaGetSymbolAddress((void**)&w2t, g_w2t);
    cudaGetSymbolAddress((void**)&masks, g_masks);

    constexpr int SM16   = 4 * 16 * 128 * 4;                 // 32 KB
    constexpr int SMEMG2 = SBK * 128 * 4 + G2_MROWS * 3 * 4; // 48.9 KB
    static bool attr_set = false;
    if (!attr_set) {
        cudaFuncSetAttribute(sgemm_nt<16>, cudaFuncAttributeMaxDynamicSharedMemorySize, SM16);
        cudaFuncSetAttribute(gemm2_sparse, cudaFuncAttributeMaxDynamicSharedMemorySize, SMEMG2);
        attr_set = true;
    }

    const int BH4 = BATCH * HID / 4;             // 102400
    const dim3 grid((HID + 127) / 128, M_ROWS / 128);

    // 0) W2 -> W2T
    {
        dim3 tg(HID / 32, HID / 32);
        transpose_w2<<<tg, dim3(32, 8)>>>(W2, w2t);
    }

    // 1) C1 = X @ W1^T + b1   (dense scalar SGEMM, K=784, BK=16)
    sgemm_nt<16><<<grid, 256, SM16>>>(x, W1, b1, c1, M_ROWS, HID, DIN);

    // 2) LIF1 -> s1r + spike masks (flat word layout)
    lif1_mask<<<BH4 / 256, 256>>>((const float4*)c1, (float4*)s1r, masks, beta1);

    // 3) sparse GEMM2: C2 = S1 @ W2^T + b2 (SBK=96, 4 blocks/SM)
    {
        dim3 sg((HID + 127) / 128, M_ROWS / G2_MROWS);   // 7 x 400
        gemm2_sparse<<<sg, 256, SMEMG2>>>(masks, w2t, b2, c2);
    }

    // 4) LIF2 -> s2r
    lif_kernel4<<<(BH4 + 255) / 256, 256>>>((const float4*)c2, (float4*)s2r, beta2, BH4);

    // 5) C3 = S2 @ W3^T + b3
    gemm3_kernel<<<M_ROWS / 8, 256>>>(s2r, W3, b3, c3, M_ROWS);

    // 6) LIF3 + sum
    lif3_kernel<<<(BATCH * NOUT + 255) / 256, 256>>>(c3, s3r, out, beta3);
}